// round 15
// baseline (speedup 1.0000x reference)
#include <cuda_runtime.h>
#include <cstdint>

#define NB 256   // batch
#define NH 2048  // hidden
#define NG 6144  // 3*H
#define NT 512   // time steps
#define NO 14    // output classes

#define NBLK 128 // persistent blocks, tile grid 2 (M) x 64 (N)
#define NTHR 128 // 4 warps: 2x2 warp grid, warp tile 64x48
#define NW   4
#define BK 32    // k per staged iteration
#define KITERS (NH / BK)
#define LDA 36   // smem row stride floats (36 mod 32 = 4 -> conflict-free frags)

#define TM 128   // block tile M
#define TN 96    // block tile N
#define TA_F (TM * LDA)             // 4608 words per A tile (hi or lo)
#define TB_F (TN * LDA)             // 3456 words
#define ST_F (2 * TA_F + TB_F)      // 12672 words per stage (Ahi | Alo | B)
#define NSTG 4
#define SMEM_DYN (NSTG * ST_F * 4)  // 202752 B
#define ST_V4 2816                  // float4 loads per stage

// ---- device-global scratch (no allocations allowed) ----
__device__ __align__(16) float    g_gh[NB * NG];        // gh scratch, 6 MB
__device__ __align__(16) float    g_h[2 * NB * NH];     // fp32 hidden, ping-pong
__device__ __align__(16) uint32_t g_hhi[2 * NB * NH];   // tf32 hi of h, ping-pong
__device__ __align__(16) uint32_t g_hlo[2 * NB * NH];   // tf32 lo of h, ping-pong
__device__ int   g_topi[NB];
__device__ unsigned g_bar_count;
__device__ unsigned g_bar_gen;

// =====================================================================
// helpers
// =====================================================================
__device__ __forceinline__ uint32_t smem_u32(const void* p) {
    uint32_t a;
    asm("{ .reg .u64 t; cvta.to.shared.u64 t, %1; cvt.u32.u64 %0, t; }"
        : "=r"(a) : "l"(p));
    return a;
}

#define CP_ASYNC16(saddr, gptr) \
    asm volatile("cp.async.cg.shared.global [%0], [%1], 16;" \
                 :: "r"(saddr), "l"(gptr) : "memory")
#define CP_COMMIT()  asm volatile("cp.async.commit_group;" ::: "memory")
#define CP_WAIT(n)   asm volatile("cp.async.wait_group %0;" :: "n"(n) : "memory")

// tf32 split: v = hi + lo, both tf32-representable (round-to-nearest)
__device__ __forceinline__ void tf32_split(float v, uint32_t& hi, uint32_t& lo) {
    asm("cvt.rna.tf32.f32 %0, %1;" : "=r"(hi) : "f"(v));
    float rl = v - __uint_as_float(hi);
    asm("cvt.rna.tf32.f32 %0, %1;" : "=r"(lo) : "f"(rl));
}

// C += A(16x8,row) * B(8x8,col)   tf32 -> f32
#define MMA8(c, a0, a1, a2, a3, b0, b1) \
    asm volatile("mma.sync.aligned.m16n8k8.row.col.f32.tf32.tf32.f32 " \
        "{%0,%1,%2,%3},{%4,%5,%6,%7},{%8,%9},{%0,%1,%2,%3};" \
        : "+f"((c)[0]), "+f"((c)[1]), "+f"((c)[2]), "+f"((c)[3]) \
        : "r"(a0), "r"(a1), "r"(a2), "r"(a3), "r"(b0), "r"(b1))

// =====================================================================
// Software grid barrier (all NBLK blocks co-resident; 128 <= 148 SMs)
// =====================================================================
__device__ __forceinline__ void grid_bar()
{
    __syncthreads();
    if (threadIdx.x == 0) {
        __threadfence();
        unsigned gen = *(volatile unsigned*)&g_bar_gen;
        unsigned arr = atomicAdd(&g_bar_count, 1u);
        if (arr == NBLK - 1) {
            *(volatile unsigned*)&g_bar_count = 0u;
            __threadfence();
            *(volatile unsigned*)&g_bar_gen = gen + 1u;
        } else {
            while (*(volatile unsigned*)&g_bar_gen == gen) { __nanosleep(64); }
        }
        __threadfence();
    }
    __syncthreads();
}

// =====================================================================
// persistent kernel for the full 512-step decode
// =====================================================================
__global__ __launch_bounds__(NTHR, 1)
void decoder_kernel(const float* __restrict__ enc_h,
                    const float* __restrict__ target,
                    const float* __restrict__ W_ih,
                    const float* __restrict__ W_hh,
                    const float* __restrict__ b_ih,
                    const float* __restrict__ b_hh,
                    const float* __restrict__ W_out,
                    const float* __restrict__ b_out,
                    float* __restrict__ out)
{
    extern __shared__ float smf[];            // NSTG stages of (Ahi | Alo | B)
    __shared__ int   s_sel[NB];               // block-local feedback select
    __shared__ float s_red[NW][NO];           // logits cross-warp reduce
    __shared__ float s_l[NO];

    const int tid = threadIdx.x;
    const int w   = tid >> 5;        // warp 0..3
    const int lid = tid & 31;
    const int gid = lid >> 2;        // 0..7
    const int tig = lid & 3;         // 0..3
    const int wm  = w >> 1;          // 0..1 : warp row (64 M)
    const int wn  = w & 1;           // 0..1 : warp col (48 N)
    const int blk  = blockIdx.x;
    const int m0   = (blk >> 6) * TM;     // 0 or 128
    const int n0   = (blk & 63) * TN;     // 0..6048
    const int gtid = blk * NTHR + tid;
    const int NTOT = NBLK * NTHR;

    const uint32_t sb = smem_u32(smf);

    // ------------- prologue: split enc_h into slot 1 ---------------------
    // (t=0 reads slot (1 - par) = 1)
    for (size_t i = (size_t)gtid * 4; i < (size_t)NB * NH; i += (size_t)NTOT * 4) {
        float4 v = *(const float4*)(enc_h + i);
        uint32_t h0, l0, h1, l1, h2, l2, h3, l3;
        tf32_split(v.x, h0, l0); tf32_split(v.y, h1, l1);
        tf32_split(v.z, h2, l2); tf32_split(v.w, h3, l3);
        *(uint4*)(g_hhi + (size_t)NB * NH + i) = make_uint4(h0, h1, h2, h3);
        *(uint4*)(g_hlo + (size_t)NB * NH + i) = make_uint4(l0, l1, l2, l3);
    }
    grid_bar();

    for (int t = 0; t < NT; t++) {
        const int par = t & 1;
        const float* hprev = (t == 0) ? enc_h : (g_h + (size_t)(1 - par) * NB * NH);
        const size_t aslot = (size_t)(1 - par) * NB * NH;

        // ================= GEMM: g_gh = hprev @ W_hh^T ==================
        {
            const uint32_t* Aih = g_hhi + aslot + (size_t)m0 * NH;
            const uint32_t* Ail = g_hlo + aslot + (size_t)m0 * NH;
            const float*    Bg  = W_hh  + (size_t)n0 * NH;

            float acc[4][6][4];
#pragma unroll
            for (int i = 0; i < 4; i++)
#pragma unroll
                for (int j = 0; j < 6; j++)
#pragma unroll
                    for (int c = 0; c < 4; c++) acc[i][j][c] = 0.f;

            // stage(bs, k0): Ahi 1024 + Alo 1024 + B 768 float4 = 2816 v4
#define STAGE(bs, k0) do {                                                    \
    const uint32_t sst = sb + (uint32_t)(bs) * (ST_F * 4u);                   \
    _Pragma("unroll")                                                         \
    for (int i = 0; i < 22; i++) {                                            \
        int idx = tid + i * NTHR;                                             \
        if (idx < 1024) {                                                     \
            int row = idx >> 3, c4 = (idx & 7) << 2;                          \
            CP_ASYNC16(sst + (uint32_t)(row * LDA + c4) * 4u,                 \
                       Aih + (size_t)row * NH + (k0) + c4);                   \
        } else if (idx < 2048) {                                              \
            int jx = idx - 1024;                                              \
            int row = jx >> 3, c4 = (jx & 7) << 2;                            \
            CP_ASYNC16(sst + (uint32_t)(TA_F + row * LDA + c4) * 4u,          \
                       Ail + (size_t)row * NH + (k0) + c4);                   \
        } else {                                                              \
            int jx = idx - 2048;                                              \
            int row = jx >> 3, c4 = (jx & 7) << 2;                            \
            CP_ASYNC16(sst + (uint32_t)(2 * TA_F + row * LDA + c4) * 4u,      \
                       Bg + (size_t)row * NH + (k0) + c4);                    \
        }                                                                     \
    }                                                                         \
    CP_COMMIT();                                                              \
} while (0)

            // prologue: stages 0..2 in flight (3 committed groups)
            STAGE(0, 0);
            STAGE(1, BK);
            STAGE(2, 2 * BK);

            // block-local scan of topi(t-1) -> s_sel (warp 0)
            if (t > 0 && w == 0) {
                int tp[8]; int hit[8]; unsigned chunk = 0;
#pragma unroll
                for (int i = 0; i < 8; i++) {
                    tp[i]  = g_topi[lid * 8 + i];
                    hit[i] = (tp[i] == NO - 1);
                    chunk |= (unsigned)hit[i];
                }
                unsigned inc = chunk;
#pragma unroll
                for (int off = 1; off < 32; off <<= 1) {
                    unsigned v = __shfl_up_sync(0xffffffffu, inc, off);
                    if (lid >= off) inc |= v;
                }
                unsigned excl = __shfl_up_sync(0xffffffffu, inc, 1);
                unsigned run  = (lid == 0) ? 0u : excl;
#pragma unroll
                for (int i = 0; i < 8; i++) {
                    int alive = !(run | (unsigned)hit[i]);
                    s_sel[lid * 8 + i] = alive ? tp[i] : -1;
                    run |= (unsigned)hit[i];
                }
            }

            for (int it = 0; it < KITERS; it++) {
                CP_WAIT(2);           // stage 'it' landed (this thread)
                __syncthreads();      // all threads: data visible, old buf free
                if (it + 3 < KITERS) {
                    STAGE((it + 3) & 3, (it + 3) * BK);
                } else {
                    CP_COMMIT();      // empty group keeps wait accounting exact
                }

                const uint32_t* Ah = (const uint32_t*)(smf + (it & 3) * ST_F);
                const uint32_t* Al = Ah + TA_F;
                const float*    Bs = (const float*)(Ah + 2 * TA_F);

#pragma unroll
                for (int ks = 0; ks < 4; ks++) {
                    const int kc = ks * 8 + tig;

                    // ---- load ALL fragments for this k-slice ----
                    uint32_t bh[6][2], bl[6][2];
#pragma unroll
                    for (int nf = 0; nf < 6; nf++) {
                        const int bb = (wn * 48 + nf * 8 + gid) * LDA + kc;
                        tf32_split(Bs[bb],     bh[nf][0], bl[nf][0]);
                        tf32_split(Bs[bb + 4], bh[nf][1], bl[nf][1]);
                    }
                    uint32_t ah[4][4], al[4][4];
#pragma unroll
                    for (int mf = 0; mf < 4; mf++) {
                        const int ab = (wm * 64 + mf * 16 + gid) * LDA + kc;
                        ah[mf][0] = Ah[ab];                al[mf][0] = Al[ab];
                        ah[mf][1] = Ah[ab + 8 * LDA];      al[mf][1] = Al[ab + 8 * LDA];
                        ah[mf][2] = Ah[ab + 4];            al[mf][2] = Al[ab + 4];
                        ah[mf][3] = Ah[ab + 8 * LDA + 4];  al[mf][3] = Al[ab + 8 * LDA + 4];
                    }

                    // ---- term-major MMA passes: no same-acc back-to-back ----
#pragma unroll
                    for (int mf = 0; mf < 4; mf++)
#pragma unroll
                        for (int nf = 0; nf < 6; nf++)
                            MMA8(acc[mf][nf], al[mf][0], al[mf][1], al[mf][2], al[mf][3],
                                 bh[nf][0], bh[nf][1]);
#pragma unroll
                    for (int mf = 0; mf < 4; mf++)
#pragma unroll
                        for (int nf = 0; nf < 6; nf++)
                            MMA8(acc[mf][nf], ah[mf][0], ah[mf][1], ah[mf][2], ah[mf][3],
                                 bl[nf][0], bl[nf][1]);
#pragma unroll
                    for (int mf = 0; mf < 4; mf++)
#pragma unroll
                        for (int nf = 0; nf < 6; nf++)
                            MMA8(acc[mf][nf], ah[mf][0], ah[mf][1], ah[mf][2], ah[mf][3],
                                 bh[nf][0], bh[nf][1]);
                }
            }
#undef STAGE

            // epilogue: registers -> g_gh
#pragma unroll
            for (int mf = 0; mf < 4; mf++) {
                const int row = m0 + wm * 64 + mf * 16 + gid;
#pragma unroll
                for (int nf = 0; nf < 6; nf++) {
                    const int col = n0 + wn * 48 + nf * 8 + 2 * tig;
                    float2 v0 = make_float2(acc[mf][nf][0], acc[mf][nf][1]);
                    float2 v1 = make_float2(acc[mf][nf][2], acc[mf][nf][3]);
                    *(float2*)(g_gh + (size_t)row * NG + col)       = v0;
                    *(float2*)(g_gh + (size_t)(row + 8) * NG + col) = v1;
                }
            }
        }
        grid_bar();   // g_gh ready everywhere

        // ========== fused gate + logits: 2 full rows per block ==========
        {
            float* hnew = g_h + (size_t)par * NB * NH;
            const size_t wslot = (size_t)par * NB * NH;
#pragma unroll 1
            for (int b = blk; b < NB; b += NBLK) {   // exactly 2 rows
                float lacc[NO];
#pragma unroll
                for (int o = 0; o < NO; o++) lacc[o] = 0.f;

                const int s = (t > 0) ? s_sel[b] : 0;

#pragma unroll 1
                for (int j = tid; j < NH; j += NTHR) {
                    float ghr = g_gh[(size_t)b * NG + j]          + b_hh[j];
                    float ghz = g_gh[(size_t)b * NG + NH + j]     + b_hh[NH + j];
                    float ghn = g_gh[(size_t)b * NG + 2 * NH + j] + b_hh[2 * NH + j];
                    float gir = b_ih[j], giz = b_ih[NH + j], gin = b_ih[2 * NH + j];

                    if (t == 0) {
#pragma unroll
                        for (int o = 0; o < NO; o++) {
                            float xv = fmaxf(target[(size_t)b * NT * NO + o], 0.f);
                            gir = fmaf(xv, W_ih[(size_t)j * NO + o], gir);
                            giz = fmaf(xv, W_ih[(size_t)(NH + j) * NO + o], giz);
                            gin = fmaf(xv, W_ih[(size_t)(2 * NH + j) * NO + o], gin);
                        }
                    } else if (s >= 0) {
                        gir += W_ih[(size_t)j * NO + s];
                        giz += W_ih[(size_t)(NH + j) * NO + s];
                        gin += W_ih[(size_t)(2 * NH + j) * NO + s];
                    }

                    float r  = 1.f / (1.f + expf(-(gir + ghr)));
                    float z  = 1.f / (1.f + expf(-(giz + ghz)));
                    float n  = tanhf(gin + r * ghn);
                    float hp = hprev[(size_t)b * NH + j];
                    float hv = (1.f - z) * n + z * hp;
                    hnew[(size_t)b * NH + j] = hv;

                    // split h for next step's GEMM A operand (coalesced)
                    uint32_t shi, slo;
                    tf32_split(hv, shi, slo);
                    g_hhi[wslot + (size_t)b * NH + j] = shi;
                    g_hlo[wslot + (size_t)b * NH + j] = slo;

                    // logits partial: h stays in registers
#pragma unroll
                    for (int o = 0; o < NO; o++)
                        lacc[o] = fmaf(hv, W_out[(size_t)o * NH + j], lacc[o]);
                }

                // reduce 14 partials over 128 threads
#pragma unroll
                for (int o = 0; o < NO; o++) {
#pragma unroll
                    for (int off = 16; off > 0; off >>= 1)
                        lacc[o] += __shfl_xor_sync(0xffffffffu, lacc[o], off);
                }
                if (lid == 0) {
#pragma unroll
                    for (int o = 0; o < NO; o++) s_red[w][o] = lacc[o];
                }
                __syncthreads();
                if (tid < NO) {
                    float l = b_out[tid];
#pragma unroll
                    for (int ww = 0; ww < NW; ww++) l += s_red[ww][tid];
                    s_l[tid] = l;
                }
                __syncthreads();
                if (tid == 0) {
                    float l[NO];
                    float m = -1e30f;
#pragma unroll
                    for (int o = 0; o < NO; o++) { l[o] = s_l[o]; m = fmaxf(m, l[o]); }
                    int   bi = 0;
                    float bv = l[0];
#pragma unroll
                    for (int o = 1; o < NO; o++)
                        if (l[o] > bv) { bv = l[o]; bi = o; }   // first-max = jnp.argmax
                    float ssum = 0.f;
#pragma unroll
                    for (int o = 0; o < NO; o++) ssum += expf(l[o] - m);
                    float lse = m + logf(ssum);
                    float* dst = out + ((size_t)b * NT + t) * NO;
#pragma unroll
                    for (int o = 0; o < NO; o++) dst[o] = l[o] - lse;
                    g_topi[b] = bi;
                }
                __syncthreads();
            }
        }
        grid_bar();   // h(t), topi(t), splits ready everywhere
    }

    // ---------------- tail: append h_final ------------------------------
    {
        const float* hf = g_h + (size_t)((NT - 1) & 1) * NB * NH;
        float* tail = out + (size_t)NB * NT * NO;
        for (int i = gtid; i < NB * NH / 4; i += NTOT) {
            float4 v = *(const float4*)(hf + (size_t)i * 4);
            *(float4*)(tail + (size_t)i * 4) = v;
        }
    }
}

// =====================================================================
extern "C" void kernel_launch(void* const* d_in, const int* in_sizes, int n_in,
                              void* d_out, int out_size)
{
    // inputs: 0 encoder_outputs (unused), 1 encoder_hidden, 2 target_tensor,
    //         3 W_ih, 4 W_hh, 5 b_ih, 6 b_hh, 7 W_out, 8 b_out
    const float* enc_h  = (const float*)d_in[1];
    const float* target = (const float*)d_in[2];
    const float* W_ih   = (const float*)d_in[3];
    const float* W_hh   = (const float*)d_in[4];
    const float* b_ih   = (const float*)d_in[5];
    const float* b_hh   = (const float*)d_in[6];
    const float* W_out  = (const float*)d_in[7];
    const float* b_out  = (const float*)d_in[8];
    float* out = (float*)d_out;

    cudaFuncSetAttribute(decoder_kernel,
                         cudaFuncAttributeMaxDynamicSharedMemorySize, SMEM_DYN);

    decoder_kernel<<<NBLK, NTHR, SMEM_DYN>>>(enc_h, target, W_ih, W_hh,
                                             b_ih, b_hh, W_out, b_out, out);
}

// round 16
// speedup vs baseline: 1.1410x; 1.1410x over previous
#include <cuda_runtime.h>
#include <cstdint>

#define NB 256   // batch
#define NH 2048  // hidden
#define NG 6144  // 3*H
#define NT 512   // time steps
#define NO 14    // output classes

#define NBLK 128 // persistent blocks, tile grid 2 (M) x 64 (N)
#define NTHR 256 // 8 warps: 2x4 warp grid, warp tile 64x24
#define NW   8
#define BK 32    // k per staged iteration
#define KITERS (NH / BK)
#define LDA 36   // smem row stride floats (36 mod 32 = 4 -> conflict-free frags)

#define TM 128   // block tile M
#define TN 96    // block tile N
#define TA_F (TM * LDA)             // 4608 words per A tile (hi or lo)
#define TB_F (TN * LDA)             // 3456 words
#define ST_F (2 * TA_F + TB_F)      // 12672 words per stage (Ahi | Alo | B)
#define NSTG 4
#define SMEM_DYN (NSTG * ST_F * 4)  // 202752 B
#define ST_V4 2816                  // float4 loads per stage (11 * 256)

// ---- device-global scratch (no allocations allowed) ----
__device__ __align__(16) float    g_gh[NB * NG];        // gh scratch, 6 MB
__device__ __align__(16) float    g_h[2 * NB * NH];     // fp32 hidden, ping-pong
__device__ __align__(16) uint32_t g_hhi[2 * NB * NH];   // tf32 hi of h, ping-pong
__device__ __align__(16) uint32_t g_hlo[2 * NB * NH];   // tf32 lo of h, ping-pong
__device__ int   g_topi[NB];
__device__ unsigned g_bar_count;
__device__ unsigned g_bar_gen;

// =====================================================================
// helpers
// =====================================================================
__device__ __forceinline__ uint32_t smem_u32(const void* p) {
    uint32_t a;
    asm("{ .reg .u64 t; cvta.to.shared.u64 t, %1; cvt.u32.u64 %0, t; }"
        : "=r"(a) : "l"(p));
    return a;
}

#define CP_ASYNC16(saddr, gptr) \
    asm volatile("cp.async.cg.shared.global [%0], [%1], 16;" \
                 :: "r"(saddr), "l"(gptr) : "memory")
#define CP_COMMIT()  asm volatile("cp.async.commit_group;" ::: "memory")
#define CP_WAIT(n)   asm volatile("cp.async.wait_group %0;" :: "n"(n) : "memory")

// tf32 split: v = hi + lo, both tf32-representable (round-to-nearest)
__device__ __forceinline__ void tf32_split(float v, uint32_t& hi, uint32_t& lo) {
    asm("cvt.rna.tf32.f32 %0, %1;" : "=r"(hi) : "f"(v));
    float rl = v - __uint_as_float(hi);
    asm("cvt.rna.tf32.f32 %0, %1;" : "=r"(lo) : "f"(rl));
}

// C += A(16x8,row) * B(8x8,col)   tf32 -> f32
#define MMA8(c, a0, a1, a2, a3, b0, b1) \
    asm volatile("mma.sync.aligned.m16n8k8.row.col.f32.tf32.tf32.f32 " \
        "{%0,%1,%2,%3},{%4,%5,%6,%7},{%8,%9},{%0,%1,%2,%3};" \
        : "+f"((c)[0]), "+f"((c)[1]), "+f"((c)[2]), "+f"((c)[3]) \
        : "r"(a0), "r"(a1), "r"(a2), "r"(a3), "r"(b0), "r"(b1))

// =====================================================================
// Software grid barrier (all NBLK blocks co-resident; 128 <= 148 SMs)
// =====================================================================
__device__ __forceinline__ void grid_bar()
{
    __syncthreads();
    if (threadIdx.x == 0) {
        __threadfence();
        unsigned gen = *(volatile unsigned*)&g_bar_gen;
        unsigned arr = atomicAdd(&g_bar_count, 1u);
        if (arr == NBLK - 1) {
            *(volatile unsigned*)&g_bar_count = 0u;
            __threadfence();
            *(volatile unsigned*)&g_bar_gen = gen + 1u;
        } else {
            while (*(volatile unsigned*)&g_bar_gen == gen) { __nanosleep(64); }
        }
        __threadfence();
    }
    __syncthreads();
}

// =====================================================================
// persistent kernel for the full 512-step decode
// =====================================================================
__global__ __launch_bounds__(NTHR, 1)
void decoder_kernel(const float* __restrict__ enc_h,
                    const float* __restrict__ target,
                    const float* __restrict__ W_ih,
                    const float* __restrict__ W_hh,
                    const float* __restrict__ b_ih,
                    const float* __restrict__ b_hh,
                    const float* __restrict__ W_out,
                    const float* __restrict__ b_out,
                    float* __restrict__ out)
{
    extern __shared__ float smf[];            // NSTG stages of (Ahi | Alo | B)
    __shared__ int   s_sel[NB];               // block-local feedback select
    __shared__ float s_red[NW][NO];           // logits cross-warp reduce
    __shared__ float s_l[NO];

    const int tid = threadIdx.x;
    const int w   = tid >> 5;        // warp 0..7
    const int lid = tid & 31;
    const int gid = lid >> 2;        // 0..7
    const int tig = lid & 3;         // 0..3
    const int wm  = w >> 2;          // 0..1 : warp row (64 M)
    const int wn  = w & 3;           // 0..3 : warp col (24 N)
    const int blk  = blockIdx.x;
    const int m0   = (blk >> 6) * TM;     // 0 or 128
    const int n0   = (blk & 63) * TN;     // 0..6048
    const int gtid = blk * NTHR + tid;
    const int NTOT = NBLK * NTHR;

    const uint32_t sb = smem_u32(smf);

    // ------------- prologue: split enc_h into slot 1 ---------------------
    // (t=0 reads slot (1 - par) = 1)
    for (size_t i = (size_t)gtid * 4; i < (size_t)NB * NH; i += (size_t)NTOT * 4) {
        float4 v = *(const float4*)(enc_h + i);
        uint32_t h0, l0, h1, l1, h2, l2, h3, l3;
        tf32_split(v.x, h0, l0); tf32_split(v.y, h1, l1);
        tf32_split(v.z, h2, l2); tf32_split(v.w, h3, l3);
        *(uint4*)(g_hhi + (size_t)NB * NH + i) = make_uint4(h0, h1, h2, h3);
        *(uint4*)(g_hlo + (size_t)NB * NH + i) = make_uint4(l0, l1, l2, l3);
    }
    grid_bar();

    for (int t = 0; t < NT; t++) {
        const int par = t & 1;
        const float* hprev = (t == 0) ? enc_h : (g_h + (size_t)(1 - par) * NB * NH);
        const size_t aslot = (size_t)(1 - par) * NB * NH;

        // ================= GEMM: g_gh = hprev @ W_hh^T ==================
        {
            const uint32_t* Aih = g_hhi + aslot + (size_t)m0 * NH;
            const uint32_t* Ail = g_hlo + aslot + (size_t)m0 * NH;
            const float*    Bg  = W_hh  + (size_t)n0 * NH;

            float acc[4][3][4];
#pragma unroll
            for (int i = 0; i < 4; i++)
#pragma unroll
                for (int j = 0; j < 3; j++)
#pragma unroll
                    for (int c = 0; c < 4; c++) acc[i][j][c] = 0.f;

            // stage(bs, k0): Ahi 1024 + Alo 1024 + B 768 float4 = 2816 v4
#define STAGE(bs, k0) do {                                                    \
    const uint32_t sst = sb + (uint32_t)(bs) * (ST_F * 4u);                   \
    _Pragma("unroll")                                                         \
    for (int i = 0; i < 11; i++) {                                            \
        int idx = tid + i * NTHR;                                             \
        if (idx < 1024) {                                                     \
            int row = idx >> 3, c4 = (idx & 7) << 2;                          \
            CP_ASYNC16(sst + (uint32_t)(row * LDA + c4) * 4u,                 \
                       Aih + (size_t)row * NH + (k0) + c4);                   \
        } else if (idx < 2048) {                                              \
            int jx = idx - 1024;                                              \
            int row = jx >> 3, c4 = (jx & 7) << 2;                            \
            CP_ASYNC16(sst + (uint32_t)(TA_F + row * LDA + c4) * 4u,          \
                       Ail + (size_t)row * NH + (k0) + c4);                   \
        } else {                                                              \
            int jx = idx - 2048;                                              \
            int row = jx >> 3, c4 = (jx & 7) << 2;                            \
            CP_ASYNC16(sst + (uint32_t)(2 * TA_F + row * LDA + c4) * 4u,      \
                       Bg + (size_t)row * NH + (k0) + c4);                    \
        }                                                                     \
    }                                                                         \
    CP_COMMIT();                                                              \
} while (0)

            // prologue: stages 0..2 in flight (3 committed groups)
            STAGE(0, 0);
            STAGE(1, BK);
            STAGE(2, 2 * BK);

            // block-local scan of topi(t-1) -> s_sel (warp 0)
            if (t > 0 && w == 0) {
                int tp[8]; int hit[8]; unsigned chunk = 0;
#pragma unroll
                for (int i = 0; i < 8; i++) {
                    tp[i]  = g_topi[lid * 8 + i];
                    hit[i] = (tp[i] == NO - 1);
                    chunk |= (unsigned)hit[i];
                }
                unsigned inc = chunk;
#pragma unroll
                for (int off = 1; off < 32; off <<= 1) {
                    unsigned v = __shfl_up_sync(0xffffffffu, inc, off);
                    if (lid >= off) inc |= v;
                }
                unsigned excl = __shfl_up_sync(0xffffffffu, inc, 1);
                unsigned run  = (lid == 0) ? 0u : excl;
#pragma unroll
                for (int i = 0; i < 8; i++) {
                    int alive = !(run | (unsigned)hit[i]);
                    s_sel[lid * 8 + i] = alive ? tp[i] : -1;
                    run |= (unsigned)hit[i];
                }
            }

            for (int it = 0; it < KITERS; it++) {
                CP_WAIT(2);           // stage 'it' landed (this thread)
                __syncthreads();      // all threads: data visible, old buf free
                if (it + 3 < KITERS) {
                    STAGE((it + 3) & 3, (it + 3) * BK);
                } else {
                    CP_COMMIT();      // empty group keeps wait accounting exact
                }

                const uint32_t* Ah = (const uint32_t*)(smf + (it & 3) * ST_F);
                const uint32_t* Al = Ah + TA_F;
                const float*    Bs = (const float*)(Ah + 2 * TA_F);

#pragma unroll
                for (int ks = 0; ks < 4; ks++) {
                    const int kc = ks * 8 + tig;

                    // ---- preload ALL fragments for this k-slice ----
                    uint32_t bh[3][2], bl[3][2];
#pragma unroll
                    for (int nf = 0; nf < 3; nf++) {
                        const int bb = (wn * 24 + nf * 8 + gid) * LDA + kc;
                        tf32_split(Bs[bb],     bh[nf][0], bl[nf][0]);
                        tf32_split(Bs[bb + 4], bh[nf][1], bl[nf][1]);
                    }
                    uint32_t ah[4][4], al[4][4];
#pragma unroll
                    for (int mf = 0; mf < 4; mf++) {
                        const int ab = (wm * 64 + mf * 16 + gid) * LDA + kc;
                        ah[mf][0] = Ah[ab];                al[mf][0] = Al[ab];
                        ah[mf][1] = Ah[ab + 8 * LDA];      al[mf][1] = Al[ab + 8 * LDA];
                        ah[mf][2] = Ah[ab + 4];            al[mf][2] = Al[ab + 4];
                        ah[mf][3] = Ah[ab + 8 * LDA + 4];  al[mf][3] = Al[ab + 8 * LDA + 4];
                    }

                    // ---- term-major passes: 12-MMA reuse distance per acc ----
#pragma unroll
                    for (int mf = 0; mf < 4; mf++)
#pragma unroll
                        for (int nf = 0; nf < 3; nf++)
                            MMA8(acc[mf][nf], al[mf][0], al[mf][1], al[mf][2], al[mf][3],
                                 bh[nf][0], bh[nf][1]);
#pragma unroll
                    for (int mf = 0; mf < 4; mf++)
#pragma unroll
                        for (int nf = 0; nf < 3; nf++)
                            MMA8(acc[mf][nf], ah[mf][0], ah[mf][1], ah[mf][2], ah[mf][3],
                                 bl[nf][0], bl[nf][1]);
#pragma unroll
                    for (int mf = 0; mf < 4; mf++)
#pragma unroll
                        for (int nf = 0; nf < 3; nf++)
                            MMA8(acc[mf][nf], ah[mf][0], ah[mf][1], ah[mf][2], ah[mf][3],
                                 bh[nf][0], bh[nf][1]);
                }
            }
#undef STAGE

            // epilogue: registers -> g_gh
#pragma unroll
            for (int mf = 0; mf < 4; mf++) {
                const int row = m0 + wm * 64 + mf * 16 + gid;
#pragma unroll
                for (int nf = 0; nf < 3; nf++) {
                    const int col = n0 + wn * 24 + nf * 8 + 2 * tig;
                    float2 v0 = make_float2(acc[mf][nf][0], acc[mf][nf][1]);
                    float2 v1 = make_float2(acc[mf][nf][2], acc[mf][nf][3]);
                    *(float2*)(g_gh + (size_t)row * NG + col)       = v0;
                    *(float2*)(g_gh + (size_t)(row + 8) * NG + col) = v1;
                }
            }
        }
        grid_bar();   // g_gh ready everywhere

        // ========== fused gate + logits: 2 full rows per block ==========
        {
            float* hnew = g_h + (size_t)par * NB * NH;
            const size_t wslot = (size_t)par * NB * NH;
#pragma unroll 1
            for (int b = blk; b < NB; b += NBLK) {   // exactly 2 rows
                float lacc[NO];
#pragma unroll
                for (int o = 0; o < NO; o++) lacc[o] = 0.f;

                const int s = (t > 0) ? s_sel[b] : 0;

#pragma unroll 1
                for (int j = tid; j < NH; j += NTHR) {
                    float ghr = g_gh[(size_t)b * NG + j]          + b_hh[j];
                    float ghz = g_gh[(size_t)b * NG + NH + j]     + b_hh[NH + j];
                    float ghn = g_gh[(size_t)b * NG + 2 * NH + j] + b_hh[2 * NH + j];
                    float gir = b_ih[j], giz = b_ih[NH + j], gin = b_ih[2 * NH + j];

                    if (t == 0) {
#pragma unroll
                        for (int o = 0; o < NO; o++) {
                            float xv = fmaxf(target[(size_t)b * NT * NO + o], 0.f);
                            gir = fmaf(xv, W_ih[(size_t)j * NO + o], gir);
                            giz = fmaf(xv, W_ih[(size_t)(NH + j) * NO + o], giz);
                            gin = fmaf(xv, W_ih[(size_t)(2 * NH + j) * NO + o], gin);
                        }
                    } else if (s >= 0) {
                        gir += W_ih[(size_t)j * NO + s];
                        giz += W_ih[(size_t)(NH + j) * NO + s];
                        gin += W_ih[(size_t)(2 * NH + j) * NO + s];
                    }

                    float r  = 1.f / (1.f + expf(-(gir + ghr)));
                    float z  = 1.f / (1.f + expf(-(giz + ghz)));
                    float n  = tanhf(gin + r * ghn);
                    float hp = hprev[(size_t)b * NH + j];
                    float hv = (1.f - z) * n + z * hp;
                    hnew[(size_t)b * NH + j] = hv;

                    // split h for next step's GEMM A operand (coalesced)
                    uint32_t shi, slo;
                    tf32_split(hv, shi, slo);
                    g_hhi[wslot + (size_t)b * NH + j] = shi;
                    g_hlo[wslot + (size_t)b * NH + j] = slo;

                    // logits partial: h stays in registers
#pragma unroll
                    for (int o = 0; o < NO; o++)
                        lacc[o] = fmaf(hv, W_out[(size_t)o * NH + j], lacc[o]);
                }

                // reduce 14 partials over 256 threads
#pragma unroll
                for (int o = 0; o < NO; o++) {
#pragma unroll
                    for (int off = 16; off > 0; off >>= 1)
                        lacc[o] += __shfl_xor_sync(0xffffffffu, lacc[o], off);
                }
                if (lid == 0) {
#pragma unroll
                    for (int o = 0; o < NO; o++) s_red[w][o] = lacc[o];
                }
                __syncthreads();
                if (tid < NO) {
                    float l = b_out[tid];
#pragma unroll
                    for (int ww = 0; ww < NW; ww++) l += s_red[ww][tid];
                    s_l[tid] = l;
                }
                __syncthreads();
                if (tid == 0) {
                    float l[NO];
                    float m = -1e30f;
#pragma unroll
                    for (int o = 0; o < NO; o++) { l[o] = s_l[o]; m = fmaxf(m, l[o]); }
                    int   bi = 0;
                    float bv = l[0];
#pragma unroll
                    for (int o = 1; o < NO; o++)
                        if (l[o] > bv) { bv = l[o]; bi = o; }   // first-max = jnp.argmax
                    float ssum = 0.f;
#pragma unroll
                    for (int o = 0; o < NO; o++) ssum += expf(l[o] - m);
                    float lse = m + logf(ssum);
                    float* dst = out + ((size_t)b * NT + t) * NO;
#pragma unroll
                    for (int o = 0; o < NO; o++) dst[o] = l[o] - lse;
                    g_topi[b] = bi;
                }
                __syncthreads();
            }
        }
        grid_bar();   // h(t), topi(t), splits ready everywhere
    }

    // ---------------- tail: append h_final ------------------------------
    {
        const float* hf = g_h + (size_t)((NT - 1) & 1) * NB * NH;
        float* tail = out + (size_t)NB * NT * NO;
        for (int i = gtid; i < NB * NH / 4; i += NTOT) {
            float4 v = *(const float4*)(hf + (size_t)i * 4);
            *(float4*)(tail + (size_t)i * 4) = v;
        }
    }
}

// =====================================================================
extern "C" void kernel_launch(void* const* d_in, const int* in_sizes, int n_in,
                              void* d_out, int out_size)
{
    // inputs: 0 encoder_outputs (unused), 1 encoder_hidden, 2 target_tensor,
    //         3 W_ih, 4 W_hh, 5 b_ih, 6 b_hh, 7 W_out, 8 b_out
    const float* enc_h  = (const float*)d_in[1];
    const float* target = (const float*)d_in[2];
    const float* W_ih   = (const float*)d_in[3];
    const float* W_hh   = (const float*)d_in[4];
    const float* b_ih   = (const float*)d_in[5];
    const float* b_hh   = (const float*)d_in[6];
    const float* W_out  = (const float*)d_in[7];
    const float* b_out  = (const float*)d_in[8];
    float* out = (float*)d_out;

    cudaFuncSetAttribute(decoder_kernel,
                         cudaFuncAttributeMaxDynamicSharedMemorySize, SMEM_DYN);

    decoder_kernel<<<NBLK, NTHR, SMEM_DYN>>>(enc_h, target, W_ih, W_hh,
                                             b_ih, b_hh, W_out, b_out, out);
}

// round 17
// speedup vs baseline: 1.7042x; 1.4936x over previous
#include <cuda_runtime.h>
#include <cuda_fp16.h>
#include <cstdint>

#define NB 256   // batch
#define NH 2048  // hidden
#define NG 6144  // 3*H
#define NT 512   // time steps
#define NO 14    // output classes

#define NBLK 128 // persistent blocks, tile grid 2 (M) x 64 (N)
#define NTHR 256 // 8 warps: 2x4 warp grid, warp tile 64x24
#define NW   8
#define BK 32    // k per staged iteration (2 x k16 MMA slices)
#define KITERS (NH / BK)

#define TM 128   // block tile M
#define TN 96    // block tile N
#define LDAH 40  // halves per smem row (80B: 16B-aligned rows, conflict-free)
#define A_HF (TM * LDAH)               // 5120 halves per A tile (hi or lo)
#define B_HF (TN * LDAH)               // 3840 halves
#define ST_HF (2 * A_HF + 2 * B_HF)    // 17920 halves per stage
#define NSTG 4
#define SMEM_DYN (NSTG * ST_HF * 2)    // 143360 B

// ---- device-global scratch (no allocations allowed) ----
__device__ __align__(16) float  g_gh[NB * NG];       // gh scratch, 6 MB
__device__ __align__(16) float  g_h[2 * NB * NH];    // fp32 hidden, ping-pong
__device__ __align__(16) __half g_Whi[NG * NH];      // fp16 hi of W_hh, 25 MB
__device__ __align__(16) __half g_Wlo[NG * NH];      // fp16 lo of W_hh, 25 MB
__device__ __align__(16) __half g_hhi[2 * NB * NH];  // fp16 hi of h, ping-pong
__device__ __align__(16) __half g_hlo[2 * NB * NH];  // fp16 lo of h, ping-pong
__device__ int   g_topi[NB];
__device__ unsigned g_bar_count;
__device__ unsigned g_bar_gen;

// =====================================================================
// helpers
// =====================================================================
__device__ __forceinline__ uint32_t smem_u32(const void* p) {
    uint32_t a;
    asm("{ .reg .u64 t; cvta.to.shared.u64 t, %1; cvt.u32.u64 %0, t; }"
        : "=r"(a) : "l"(p));
    return a;
}

#define CP_ASYNC16(saddr, gptr) \
    asm volatile("cp.async.cg.shared.global [%0], [%1], 16;" \
                 :: "r"(saddr), "l"(gptr) : "memory")
#define CP_COMMIT()  asm volatile("cp.async.commit_group;" ::: "memory")
#define CP_WAIT(n)   asm volatile("cp.async.wait_group %0;" :: "n"(n) : "memory")

// fp16 split: v = hi + lo (hi,lo fp16; residual exact in fp32 before rounding)
__device__ __forceinline__ void h2_split(float v, __half& hi, __half& lo) {
    hi = __float2half_rn(v);
    lo = __float2half_rn(v - __half2float(hi));
}

// C += A(16x16,row,f16) * B(16x8,col,f16)  -> f32
#define MMAH(c, a0, a1, a2, a3, b0, b1) \
    asm volatile("mma.sync.aligned.m16n8k16.row.col.f32.f16.f16.f32 " \
        "{%0,%1,%2,%3},{%4,%5,%6,%7},{%8,%9},{%0,%1,%2,%3};" \
        : "+f"((c)[0]), "+f"((c)[1]), "+f"((c)[2]), "+f"((c)[3]) \
        : "r"(a0), "r"(a1), "r"(a2), "r"(a3), "r"(b0), "r"(b1))

// =====================================================================
// Software grid barrier (all NBLK blocks co-resident; 128 <= 148 SMs)
// =====================================================================
__device__ __forceinline__ void grid_bar()
{
    __syncthreads();
    if (threadIdx.x == 0) {
        __threadfence();
        unsigned gen = *(volatile unsigned*)&g_bar_gen;
        unsigned arr = atomicAdd(&g_bar_count, 1u);
        if (arr == NBLK - 1) {
            *(volatile unsigned*)&g_bar_count = 0u;
            __threadfence();
            *(volatile unsigned*)&g_bar_gen = gen + 1u;
        } else {
            while (*(volatile unsigned*)&g_bar_gen == gen) { __nanosleep(64); }
        }
        __threadfence();
    }
    __syncthreads();
}

// =====================================================================
// persistent kernel for the full 512-step decode (fp16x2-split GEMM)
// =====================================================================
__global__ __launch_bounds__(NTHR, 1)
void decoder_kernel(const float* __restrict__ enc_h,
                    const float* __restrict__ target,
                    const float* __restrict__ W_ih,
                    const float* __restrict__ W_hh,
                    const float* __restrict__ b_ih,
                    const float* __restrict__ b_hh,
                    const float* __restrict__ W_out,
                    const float* __restrict__ b_out,
                    float* __restrict__ out)
{
    extern __shared__ __half smh[];           // NSTG stages (Ahi|Alo|Bhi|Blo)
    __shared__ int   s_sel[NB];               // block-local feedback select
    __shared__ float s_red[NW][NO];           // logits cross-warp reduce
    __shared__ float s_l[NO];

    const int tid = threadIdx.x;
    const int w   = tid >> 5;        // warp 0..7
    const int lid = tid & 31;
    const int gid = lid >> 2;        // 0..7
    const int tig = lid & 3;         // 0..3
    const int wm  = w >> 2;          // 0..1 : warp row (64 M)
    const int wn  = w & 3;           // 0..3 : warp col (24 N)
    const int blk  = blockIdx.x;
    const int m0   = (blk >> 6) * TM;     // 0 or 128
    const int n0   = (blk & 63) * TN;     // 0..6048
    const int gtid = blk * NTHR + tid;
    const int NTOT = NBLK * NTHR;

    const uint32_t sb = smem_u32(smh);

    // ------------- prologue: split W_hh and enc_h to fp16 hi/lo ----------
    for (size_t i = (size_t)gtid; i < (size_t)NG * NH; i += (size_t)NTOT) {
        __half hi, lo;
        h2_split(W_hh[i], hi, lo);
        g_Whi[i] = hi;
        g_Wlo[i] = lo;
    }
    // enc_h split goes into slot 1 (t=0 reads slot (1 - par) = 1)
    for (size_t i = (size_t)gtid; i < (size_t)NB * NH; i += (size_t)NTOT) {
        __half hi, lo;
        h2_split(enc_h[i], hi, lo);
        g_hhi[(size_t)NB * NH + i] = hi;
        g_hlo[(size_t)NB * NH + i] = lo;
    }
    grid_bar();

    for (int t = 0; t < NT; t++) {
        const int par = t & 1;
        const float* hprev = (t == 0) ? enc_h : (g_h + (size_t)(1 - par) * NB * NH);
        const size_t aslot = (size_t)(1 - par) * NB * NH;

        // ================= GEMM: g_gh = hprev @ W_hh^T ==================
        {
            const __half* Aih = g_hhi + aslot + (size_t)m0 * NH;
            const __half* Ail = g_hlo + aslot + (size_t)m0 * NH;
            const __half* Bih = g_Whi + (size_t)n0 * NH;
            const __half* Bil = g_Wlo + (size_t)n0 * NH;

            float acc[4][3][4];
#pragma unroll
            for (int i = 0; i < 4; i++)
#pragma unroll
                for (int j = 0; j < 3; j++)
#pragma unroll
                    for (int c = 0; c < 4; c++) acc[i][j][c] = 0.f;

            // stage(bs, k0): Ahi 512 + Alo 512 + Bhi 384 + Blo 384 = 1792 x 16B
            //              = 7 chunks per thread. Each row: 32 halves = 4 chunks.
#define STAGE(bs, k0) do {                                                    \
    const uint32_t sst = sb + (uint32_t)(bs) * (ST_HF * 2u);                  \
    _Pragma("unroll")                                                         \
    for (int i = 0; i < 7; i++) {                                             \
        int idx = tid + i * NTHR;                                             \
        if (idx < 512) {                                                      \
            int row = idx >> 2, c8 = (idx & 3) << 3;                          \
            CP_ASYNC16(sst + (uint32_t)(row * LDAH + c8) * 2u,                \
                       Aih + (size_t)row * NH + (k0) + c8);                   \
        } else if (idx < 1024) {                                              \
            int jx = idx - 512;                                               \
            int row = jx >> 2, c8 = (jx & 3) << 3;                            \
            CP_ASYNC16(sst + (uint32_t)(A_HF + row * LDAH + c8) * 2u,         \
                       Ail + (size_t)row * NH + (k0) + c8);                   \
        } else if (idx < 1408) {                                              \
            int jx = idx - 1024;                                              \
            int row = jx >> 2, c8 = (jx & 3) << 3;                            \
            CP_ASYNC16(sst + (uint32_t)(2 * A_HF + row * LDAH + c8) * 2u,     \
                       Bih + (size_t)row * NH + (k0) + c8);                   \
        } else {                                                              \
            int jx = idx - 1408;                                              \
            int row = jx >> 2, c8 = (jx & 3) << 3;                            \
            CP_ASYNC16(sst + (uint32_t)(2 * A_HF + B_HF + row * LDAH + c8) * 2u, \
                       Bil + (size_t)row * NH + (k0) + c8);                   \
        }                                                                     \
    }                                                                         \
    CP_COMMIT();                                                              \
} while (0)

            // prologue: stages 0..2 in flight (3 committed groups)
            STAGE(0, 0);
            STAGE(1, BK);
            STAGE(2, 2 * BK);

            // block-local scan of topi(t-1) -> s_sel (warp 0)
            if (t > 0 && w == 0) {
                int tp[8]; int hit[8]; unsigned chunk = 0;
#pragma unroll
                for (int i = 0; i < 8; i++) {
                    tp[i]  = g_topi[lid * 8 + i];
                    hit[i] = (tp[i] == NO - 1);
                    chunk |= (unsigned)hit[i];
                }
                unsigned inc = chunk;
#pragma unroll
                for (int off = 1; off < 32; off <<= 1) {
                    unsigned v = __shfl_up_sync(0xffffffffu, inc, off);
                    if (lid >= off) inc |= v;
                }
                unsigned excl = __shfl_up_sync(0xffffffffu, inc, 1);
                unsigned run  = (lid == 0) ? 0u : excl;
#pragma unroll
                for (int i = 0; i < 8; i++) {
                    int alive = !(run | (unsigned)hit[i]);
                    s_sel[lid * 8 + i] = alive ? tp[i] : -1;
                    run |= (unsigned)hit[i];
                }
            }

            for (int it = 0; it < KITERS; it++) {
                CP_WAIT(2);           // stage 'it' landed (this thread)
                __syncthreads();      // all threads: data visible, old buf free
                if (it + 3 < KITERS) {
                    STAGE((it + 3) & 3, (it + 3) * BK);
                } else {
                    CP_COMMIT();      // empty group keeps wait accounting exact
                }

                const __half* Ah = smh + (it & 3) * ST_HF;
                const __half* Al = Ah + A_HF;
                const __half* Bh = Ah + 2 * A_HF;
                const __half* Bl = Bh + B_HF;

#pragma unroll
                for (int ks = 0; ks < 2; ks++) {   // two k16 slices per iter
                    const int kh = ks * 16 + tig * 2;   // half index of k-pair

                    // ---- preload ALL fragments for this k16 slice ----
                    uint32_t bh[3][2], bl[3][2];
#pragma unroll
                    for (int nf = 0; nf < 3; nf++) {
                        const int bb = (wn * 24 + nf * 8 + gid) * LDAH + kh;
                        bh[nf][0] = *(const uint32_t*)(Bh + bb);
                        bh[nf][1] = *(const uint32_t*)(Bh + bb + 8);
                        bl[nf][0] = *(const uint32_t*)(Bl + bb);
                        bl[nf][1] = *(const uint32_t*)(Bl + bb + 8);
                    }
                    uint32_t ah[4][4], al[4][4];
#pragma unroll
                    for (int mf = 0; mf < 4; mf++) {
                        const int ab = (wm * 64 + mf * 16 + gid) * LDAH + kh;
                        ah[mf][0] = *(const uint32_t*)(Ah + ab);
                        ah[mf][1] = *(const uint32_t*)(Ah + ab + 8 * LDAH);
                        ah[mf][2] = *(const uint32_t*)(Ah + ab + 8);
                        ah[mf][3] = *(const uint32_t*)(Ah + ab + 8 * LDAH + 8);
                        al[mf][0] = *(const uint32_t*)(Al + ab);
                        al[mf][1] = *(const uint32_t*)(Al + ab + 8 * LDAH);
                        al[mf][2] = *(const uint32_t*)(Al + ab + 8);
                        al[mf][3] = *(const uint32_t*)(Al + ab + 8 * LDAH + 8);
                    }

                    // ---- term-major passes: 12-MMA reuse distance per acc ----
#pragma unroll
                    for (int mf = 0; mf < 4; mf++)
#pragma unroll
                        for (int nf = 0; nf < 3; nf++)
                            MMAH(acc[mf][nf], al[mf][0], al[mf][1], al[mf][2], al[mf][3],
                                 bh[nf][0], bh[nf][1]);
#pragma unroll
                    for (int mf = 0; mf < 4; mf++)
#pragma unroll
                        for (int nf = 0; nf < 3; nf++)
                            MMAH(acc[mf][nf], ah[mf][0], ah[mf][1], ah[mf][2], ah[mf][3],
                                 bl[nf][0], bl[nf][1]);
#pragma unroll
                    for (int mf = 0; mf < 4; mf++)
#pragma unroll
                        for (int nf = 0; nf < 3; nf++)
                            MMAH(acc[mf][nf], ah[mf][0], ah[mf][1], ah[mf][2], ah[mf][3],
                                 bh[nf][0], bh[nf][1]);
                }
            }
#undef STAGE

            // epilogue: registers -> g_gh (same fp32 C layout as tf32 k8)
#pragma unroll
            for (int mf = 0; mf < 4; mf++) {
                const int row = m0 + wm * 64 + mf * 16 + gid;
#pragma unroll
                for (int nf = 0; nf < 3; nf++) {
                    const int col = n0 + wn * 24 + nf * 8 + 2 * tig;
                    float2 v0 = make_float2(acc[mf][nf][0], acc[mf][nf][1]);
                    float2 v1 = make_float2(acc[mf][nf][2], acc[mf][nf][3]);
                    *(float2*)(g_gh + (size_t)row * NG + col)       = v0;
                    *(float2*)(g_gh + (size_t)(row + 8) * NG + col) = v1;
                }
            }
        }
        grid_bar();   // g_gh ready everywhere

        // ========== fused gate + logits: 2 full rows per block ==========
        {
            float* hnew = g_h + (size_t)par * NB * NH;
            const size_t wslot = (size_t)par * NB * NH;
#pragma unroll 1
            for (int b = blk; b < NB; b += NBLK) {   // exactly 2 rows
                float lacc[NO];
#pragma unroll
                for (int o = 0; o < NO; o++) lacc[o] = 0.f;

                const int s = (t > 0) ? s_sel[b] : 0;

#pragma unroll 1
                for (int j = tid; j < NH; j += NTHR) {
                    float ghr = g_gh[(size_t)b * NG + j]          + b_hh[j];
                    float ghz = g_gh[(size_t)b * NG + NH + j]     + b_hh[NH + j];
                    float ghn = g_gh[(size_t)b * NG + 2 * NH + j] + b_hh[2 * NH + j];
                    float gir = b_ih[j], giz = b_ih[NH + j], gin = b_ih[2 * NH + j];

                    if (t == 0) {
#pragma unroll
                        for (int o = 0; o < NO; o++) {
                            float xv = fmaxf(target[(size_t)b * NT * NO + o], 0.f);
                            gir = fmaf(xv, W_ih[(size_t)j * NO + o], gir);
                            giz = fmaf(xv, W_ih[(size_t)(NH + j) * NO + o], giz);
                            gin = fmaf(xv, W_ih[(size_t)(2 * NH + j) * NO + o], gin);
                        }
                    } else if (s >= 0) {
                        gir += W_ih[(size_t)j * NO + s];
                        giz += W_ih[(size_t)(NH + j) * NO + s];
                        gin += W_ih[(size_t)(2 * NH + j) * NO + s];
                    }

                    float r  = 1.f / (1.f + expf(-(gir + ghr)));
                    float z  = 1.f / (1.f + expf(-(giz + ghz)));
                    float n  = tanhf(gin + r * ghn);
                    float hp = hprev[(size_t)b * NH + j];
                    float hv = (1.f - z) * n + z * hp;
                    hnew[(size_t)b * NH + j] = hv;

                    // fp16 split of h for next step's GEMM A operand
                    __half shi, slo;
                    h2_split(hv, shi, slo);
                    g_hhi[wslot + (size_t)b * NH + j] = shi;
                    g_hlo[wslot + (size_t)b * NH + j] = slo;

                    // logits partial: h stays in registers
#pragma unroll
                    for (int o = 0; o < NO; o++)
                        lacc[o] = fmaf(hv, W_out[(size_t)o * NH + j], lacc[o]);
                }

                // reduce 14 partials over 256 threads
#pragma unroll
                for (int o = 0; o < NO; o++) {
#pragma unroll
                    for (int off = 16; off > 0; off >>= 1)
                        lacc[o] += __shfl_xor_sync(0xffffffffu, lacc[o], off);
                }
                if (lid == 0) {
#pragma unroll
                    for (int o = 0; o < NO; o++) s_red[w][o] = lacc[o];
                }
                __syncthreads();
                if (tid < NO) {
                    float l = b_out[tid];
#pragma unroll
                    for (int ww = 0; ww < NW; ww++) l += s_red[ww][tid];
                    s_l[tid] = l;
                }
                __syncthreads();
                if (tid == 0) {
                    float l[NO];
                    float m = -1e30f;
#pragma unroll
                    for (int o = 0; o < NO; o++) { l[o] = s_l[o]; m = fmaxf(m, l[o]); }
                    int   bi = 0;
                    float bv = l[0];
#pragma unroll
                    for (int o = 1; o < NO; o++)
                        if (l[o] > bv) { bv = l[o]; bi = o; }   // first-max = jnp.argmax
                    float ssum = 0.f;
#pragma unroll
                    for (int o = 0; o < NO; o++) ssum += expf(l[o] - m);
                    float lse = m + logf(ssum);
                    float* dst = out + ((size_t)b * NT + t) * NO;
#pragma unroll
                    for (int o = 0; o < NO; o++) dst[o] = l[o] - lse;
                    g_topi[b] = bi;
                }
                __syncthreads();
            }
        }
        grid_bar();   // h(t), topi(t), splits ready everywhere
    }

    // ---------------- tail: append h_final ------------------------------
    {
        const float* hf = g_h + (size_t)((NT - 1) & 1) * NB * NH;
        float* tail = out + (size_t)NB * NT * NO;
        for (int i = gtid; i < NB * NH / 4; i += NTOT) {
            float4 v = *(const float4*)(hf + (size_t)i * 4);
            *(float4*)(tail + (size_t)i * 4) = v;
        }
    }
}

// =====================================================================
extern "C" void kernel_launch(void* const* d_in, const int* in_sizes, int n_in,
                              void* d_out, int out_size)
{
    // inputs: 0 encoder_outputs (unused), 1 encoder_hidden, 2 target_tensor,
    //         3 W_ih, 4 W_hh, 5 b_ih, 6 b_hh, 7 W_out, 8 b_out
    const float* enc_h  = (const float*)d_in[1];
    const float* target = (const float*)d_in[2];
    const float* W_ih   = (const float*)d_in[3];
    const float* W_hh   = (const float*)d_in[4];
    const float* b_ih   = (const float*)d_in[5];
    const float* b_hh   = (const float*)d_in[6];
    const float* W_out  = (const float*)d_in[7];
    const float* b_out  = (const float*)d_in[8];
    float* out = (float*)d_out;

    cudaFuncSetAttribute(decoder_kernel,
                         cudaFuncAttributeMaxDynamicSharedMemorySize, SMEM_DYN);

    decoder_kernel<<<NBLK, NTHR, SMEM_DYN>>>(enc_h, target, W_ih, W_hh,
                                             b_ih, b_hh, W_out, b_out, out);
}